// round 8
// baseline (speedup 1.0000x reference)
#include <cuda_runtime.h>
#include <math.h>

#define CCH 512
#define BB  32
#define HW  4096
#define BN_EPS 1e-5f

#define GEMM_BLOCKS 256
#define RED_BLOCKS  (BB * CCH)

// Per-(b,c) pooled values (already includes pos-embed term and /4096).
__device__ float g_pooled[BB * CCH];

// Grid-wide arrival counter (release by reduce blocks, acquire by gemm blocks).
// Zero-initialized at module load; the consumed-counter protocol below resets
// both to 0 before the kernel exits, so every replay starts clean.
__device__ volatile unsigned g_done;
__device__ unsigned g_consumed;

// 49 bilinear pooling weights A[i]*A[j], computed host-side, passed by value.
struct PEW { float w[49]; };

// ---------------------------------------------------------------------------
// Fused kernel.
//  bid <  GEMM_BLOCKS : gemm role — prefetch conv_w/BN into registers, spin on
//                       g_done (overlapping the whole reduce phase), then do
//                       the dense layer on warm weights. ~1-1.5us exposed.
//  bid >= GEMM_BLOCKS : reduce role — sum one (b,c) 64x64 plane (+pe term),
//                       store pooled, fence, arrive on g_done.
// ---------------------------------------------------------------------------
__global__ __launch_bounds__(256) void fused_kernel(
    const float* __restrict__ x,
    const float* __restrict__ pe,
    const float* __restrict__ conv_w,
    const float* __restrict__ conv_b,
    const float* __restrict__ gamma,
    const float* __restrict__ beta,
    const float* __restrict__ rmean,
    const float* __restrict__ rvar,
    float* __restrict__ out,
    PEW pw)
{
    const int t = threadIdx.x;

    if (blockIdx.x >= GEMM_BLOCKS) {
        // ================= reduce role =================
        const int bc = blockIdx.x - GEMM_BLOCKS;
        const float4* p = reinterpret_cast<const float4*>(x) + (size_t)bc * (HW / 4);

        float4 a = p[t];
        float4 b = p[t + 256];
        float4 c = p[t + 512];
        float4 d = p[t + 768];

        float s = (a.x + a.y) + (a.z + a.w)
                + (b.x + b.y) + (b.z + b.w)
                + (c.x + c.y) + (c.z + c.w)
                + (d.x + d.y) + (d.z + d.w);

        #pragma unroll
        for (int off = 16; off > 0; off >>= 1)
            s += __shfl_xor_sync(0xffffffffu, s, off);

        __shared__ float ws[8];
        const int w = t >> 5, l = t & 31;
        if (l == 0) ws[w] = s;
        __syncthreads();

        if (t < 32) {
            const int cch = bc & (CCH - 1);
            const float* pc = pe + cch * 49;
            float v = (l < 8) ? ws[l] : 0.f;
            v = fmaf(pc[l], pw.w[l], v);                       // terms 0..31
            if (l < 17) v = fmaf(pc[l + 32], pw.w[l + 32], v); // terms 32..48
            #pragma unroll
            for (int off = 16; off > 0; off >>= 1)
                v += __shfl_xor_sync(0xffffffffu, v, off);
            if (l == 0) {
                g_pooled[bc] = v * (1.0f / (float)HW);
                __threadfence();                 // release pooled value
                atomicAdd((unsigned*)&g_done, 1u);
            }
        }
        return;
    }

    // ================= gemm role =================
    const int gb = blockIdx.x;
    const int b0 = (gb & 3) * 8;        // batch group: 8 batches
    const int o0 = (gb >> 2) * 8;       // output tile: 8 outputs (1/warp)
    const int w  = t >> 5, l = t & 31;
    const int o  = o0 + w;

    // ---- Prefetch phase: runs during the entire reduce phase ----
    const float4* wr4 = reinterpret_cast<const float4*>(conv_w + (size_t)o * CCH);
    float4 wv[4];
    #pragma unroll
    for (int i = 0; i < 4; i++)
        wv[i] = wr4[l + 32 * i];

    float bias = 0.f, gm = 0.f, bt = 0.f, mu = 0.f, var1 = 1.f;
    if (l == 0) {
        bias = conv_b[o]; gm = gamma[o]; bt = beta[o];
        mu = rmean[o];    var1 = rvar[o];
    }

    // ---- Spin until all reduce blocks have arrived ----
    if (t == 0) {
        while (g_done < (unsigned)RED_BLOCKS)
            __nanosleep(128);
    }
    __syncthreads();
    __threadfence();   // acquire: order subsequent g_pooled reads after flag

    // ---- Stage pooled rows for the 8 batches (16KB smem, from L2) ----
    __shared__ float sp[8 * CCH];
    {
        const float4* src = reinterpret_cast<const float4*>(g_pooled + b0 * CCH);
        float4* dst = reinterpret_cast<float4*>(sp);
        #pragma unroll
        for (int i = 0; i < 4; i++)
            dst[t + 256 * i] = src[t + 256 * i];
    }
    __syncthreads();

    float acc[8];
    #pragma unroll
    for (int b = 0; b < 8; b++) {
        const float4* sp4 = reinterpret_cast<const float4*>(sp + b * CCH);
        float a = 0.f;
        #pragma unroll
        for (int i = 0; i < 4; i++) {
            float4 s4 = sp4[l + 32 * i];
            a = fmaf(wv[i].x, s4.x, a);
            a = fmaf(wv[i].y, s4.y, a);
            a = fmaf(wv[i].z, s4.z, a);
            a = fmaf(wv[i].w, s4.w, a);
        }
        acc[b] = a;
    }

    #pragma unroll
    for (int off = 16; off > 0; off >>= 1) {
        #pragma unroll
        for (int b = 0; b < 8; b++)
            acc[b] += __shfl_xor_sync(0xffffffffu, acc[b], off);
    }

    if (l == 0) {
        const float inv = rsqrtf(var1 + BN_EPS);
        #pragma unroll
        for (int b = 0; b < 8; b++) {
            float y = gm * (acc[b] + bias - mu) * inv + bt;
            out[(b0 + b) * CCH + o] = fmaxf(y, 0.f);
        }
    }

    // ---- Counter reset protocol (keeps replays deterministic) ----
    if (t == 0) {
        unsigned prev = atomicAdd(&g_consumed, 1u);
        if (prev == GEMM_BLOCKS - 1) {
            // All gemm blocks have passed the wait; safe to reset.
            atomicExch((unsigned*)&g_done, 0u);
            atomicExch(&g_consumed, 0u);
        }
    }
}

extern "C" void kernel_launch(void* const* d_in, const int* in_sizes, int n_in,
                              void* d_out, int out_size) {
    const float* x      = (const float*)d_in[0];
    const float* pe     = (const float*)d_in[1];
    const float* conv_w = (const float*)d_in[2];
    const float* conv_b = (const float*)d_in[3];
    const float* gamma  = (const float*)d_in[4];
    const float* beta   = (const float*)d_in[5];
    const float* rmean  = (const float*)d_in[6];
    const float* rvar   = (const float*)d_in[7];
    float* out = (float*)d_out;

    // Host-side: bilinear 7->64 (half-pixel centers) column sums A[7],
    // then outer-product weights W[i*7+j] = A[i]*A[j].
    float A[7] = {0, 0, 0, 0, 0, 0, 0};
    for (int o = 0; o < 64; o++) {
        float s = (o + 0.5f) * (7.0f / 64.0f) - 0.5f;
        if (s <= 0.f)       A[0] += 1.f;
        else if (s >= 6.f)  A[6] += 1.f;
        else {
            int i0 = (int)floorf(s);
            float f = s - (float)i0;
            A[i0]     += 1.f - f;
            A[i0 + 1] += f;
        }
    }
    PEW pw;
    for (int i = 0; i < 7; i++)
        for (int j = 0; j < 7; j++)
            pw.w[i * 7 + j] = A[i] * A[j];

    fused_kernel<<<GEMM_BLOCKS + RED_BLOCKS, 256>>>(
        x, pe, conv_w, conv_b, gamma, beta, rmean, rvar, out, pw);
}

// round 10
// speedup vs baseline: 2.3767x; 2.3767x over previous
#include <cuda_runtime.h>
#include <math.h>

#define CCH 512
#define BB  32
#define HW  4096
#define BN_EPS 1e-5f

#define RED_BLOCKS (BB * CCH)
#define PF_BLOCKS  512          // tail blocks that prefetch conv_w into L2
#define PF_FLOATS  (CCH * CCH / PF_BLOCKS)   // 512 floats = 2KB per block

// Per-(b,c) pooled values (already includes pos-embed term and /4096).
__device__ float g_pooled[BB * CCH];

// 49 bilinear pooling weights A[i]*A[j], computed host-side, passed by value.
struct PEW { float w[49]; };

// ---------------------------------------------------------------------------
// Kernel 1: pooled[b,c] = ( sum_{hw} x[b,c,:,:] + sum_k pe[c,k]*W[k] ) / 4096
// One block per (b,c). 256 threads * 4 float4 (ld.global.cs: evict-first so x
// never pollutes L2). The last PF_BLOCKS blocks — scheduled last, running in
// the final waves — additionally prefetch conv_w into L2 so the gemm kernel
// starts with a warm weight set instead of cold-DRAM misses.
// ---------------------------------------------------------------------------
__global__ __launch_bounds__(256) void reduce_x_kernel(
    const float* __restrict__ x, const float* __restrict__ pe,
    const float* __restrict__ conv_w, PEW pw)
{
    const int bc = blockIdx.x;
    const float4* p = reinterpret_cast<const float4*>(x) + (size_t)bc * (HW / 4);
    const int t = threadIdx.x;

    float4 a = __ldcs(p + t);
    float4 b = __ldcs(p + t + 256);
    float4 c = __ldcs(p + t + 512);
    float4 d = __ldcs(p + t + 768);

    float s = (a.x + a.y) + (a.z + a.w)
            + (b.x + b.y) + (b.z + b.w)
            + (c.x + c.y) + (c.z + c.w)
            + (d.x + d.y) + (d.z + d.w);

    #pragma unroll
    for (int off = 16; off > 0; off >>= 1)
        s += __shfl_xor_sync(0xffffffffu, s, off);

    __shared__ float ws[8];
    const int w = t >> 5, l = t & 31;
    if (l == 0) ws[w] = s;
    __syncthreads();

    if (t < 32) {
        const int cch = bc & (CCH - 1);
        const float* pc = pe + cch * 49;
        float v = (l < 8) ? ws[l] : 0.f;
        v = fmaf(pc[l], pw.w[l], v);                       // terms 0..31
        if (l < 17) v = fmaf(pc[l + 32], pw.w[l + 32], v); // terms 32..48
        #pragma unroll
        for (int off = 16; off > 0; off >>= 1)
            v += __shfl_xor_sync(0xffffffffu, v, off);
        if (l == 0) g_pooled[bc] = v * (1.0f / (float)HW);
    }

    // Tail L2 prefetch of conv_w (1MB total across the last PF_BLOCKS blocks;
    // 2KB = 16 x 128B lines per block, one line per thread t<16).
    if (bc >= RED_BLOCKS - PF_BLOCKS && t < 16) {
        const int pb = bc - (RED_BLOCKS - PF_BLOCKS);
        const float* base = conv_w + (size_t)pb * PF_FLOATS + t * 32;
        asm volatile("prefetch.global.L2 [%0];" :: "l"(base));
    }
}

// ---------------------------------------------------------------------------
// Kernel 2: batch-amortized dense layer on L2-warm weights.
// Block = 8 outputs (one per warp) x 8 batches. Grid = 64 o-tiles x 4 b-groups.
// Each lane caches its conv_w row segment as 4 x LDG.128, reused for 8 batches.
// ---------------------------------------------------------------------------
__global__ __launch_bounds__(256) void gemm_kernel(
    const float* __restrict__ conv_w,
    const float* __restrict__ conv_b,
    const float* __restrict__ gamma,
    const float* __restrict__ beta,
    const float* __restrict__ rmean,
    const float* __restrict__ rvar,
    float* __restrict__ out)
{
    const int b0 = (blockIdx.x & 3) * 8;        // batch group: 8 batches
    const int o0 = (blockIdx.x >> 2) * 8;       // output tile: 8 outputs
    const int t  = threadIdx.x;
    const int w  = t >> 5, l = t & 31;
    const int o  = o0 + w;

    // Weight row segment: 4 x float4 per lane (16 floats), coalesced 128B.
    const float4* wr4 = reinterpret_cast<const float4*>(conv_w + (size_t)o * CCH);
    float4 wv[4];
    #pragma unroll
    for (int i = 0; i < 4; i++)
        wv[i] = wr4[l + 32 * i];

    // Stage pooled rows for the 8 batches: 16KB smem (L2-resident source).
    __shared__ float sp[8 * CCH];
    {
        const float4* src = reinterpret_cast<const float4*>(g_pooled + b0 * CCH);
        float4* dst = reinterpret_cast<float4*>(sp);
        #pragma unroll
        for (int i = 0; i < 4; i++)
            dst[t + 256 * i] = src[t + 256 * i];
    }
    __syncthreads();

    float acc[8];
    #pragma unroll
    for (int b = 0; b < 8; b++) {
        const float4* sp4 = reinterpret_cast<const float4*>(sp + b * CCH);
        float a = 0.f;
        #pragma unroll
        for (int i = 0; i < 4; i++) {
            float4 s4 = sp4[l + 32 * i];
            a = fmaf(wv[i].x, s4.x, a);
            a = fmaf(wv[i].y, s4.y, a);
            a = fmaf(wv[i].z, s4.z, a);
            a = fmaf(wv[i].w, s4.w, a);
        }
        acc[b] = a;
    }

    #pragma unroll
    for (int off = 16; off > 0; off >>= 1) {
        #pragma unroll
        for (int b = 0; b < 8; b++)
            acc[b] += __shfl_xor_sync(0xffffffffu, acc[b], off);
    }

    if (l == 0) {
        const float bias = conv_b[o];
        const float g = gamma[o], bt = beta[o], mu = rmean[o];
        const float inv = rsqrtf(rvar[o] + BN_EPS);
        #pragma unroll
        for (int b = 0; b < 8; b++) {
            float y = g * (acc[b] + bias - mu) * inv + bt;
            out[(b0 + b) * CCH + o] = fmaxf(y, 0.f);
        }
    }
}

extern "C" void kernel_launch(void* const* d_in, const int* in_sizes, int n_in,
                              void* d_out, int out_size) {
    const float* x      = (const float*)d_in[0];
    const float* pe     = (const float*)d_in[1];
    const float* conv_w = (const float*)d_in[2];
    const float* conv_b = (const float*)d_in[3];
    const float* gamma  = (const float*)d_in[4];
    const float* beta   = (const float*)d_in[5];
    const float* rmean  = (const float*)d_in[6];
    const float* rvar   = (const float*)d_in[7];
    float* out = (float*)d_out;

    // Host-side: bilinear 7->64 (half-pixel centers) column sums A[7],
    // then outer-product weights W[i*7+j] = A[i]*A[j].
    float A[7] = {0, 0, 0, 0, 0, 0, 0};
    for (int o = 0; o < 64; o++) {
        float s = (o + 0.5f) * (7.0f / 64.0f) - 0.5f;
        if (s <= 0.f)       A[0] += 1.f;
        else if (s >= 6.f)  A[6] += 1.f;
        else {
            int i0 = (int)floorf(s);
            float f = s - (float)i0;
            A[i0]     += 1.f - f;
            A[i0 + 1] += f;
        }
    }
    PEW pw;
    for (int i = 0; i < 7; i++)
        for (int j = 0; j < 7; j++)
            pw.w[i * 7 + j] = A[i] * A[j];

    reduce_x_kernel<<<RED_BLOCKS, 256>>>(x, pe, conv_w, pw);
    gemm_kernel<<<64 * 4, 256>>>(conv_w, conv_b, gamma, beta, rmean, rvar, out);
}